// round 9
// baseline (speedup 1.0000x reference)
#include <cuda_runtime.h>

#define IMG_W    512
#define OUTW     502
#define NPLANE   48
#define IN_COLS  128
#define OUT_COLS 118
#define OUT_ROWS 8
#define IN_ROWS  18          // OUT_ROWS + 10
#define PITCH    129         // u64 units; conflict-free per 16-lane LDS.64 phase
#define KS       11
#define SEGL     8           // outputs per thread in pass 2 (16 segs x 8 = 128 >= 118)
#define GX       5
#define GY       63          // 63*8 = 504 >= 502
#define NBLOCKS  (GX * GY * NPLANE)   // 15120

typedef unsigned long long u64;

__device__ double   g_acc   = 0.0;
__device__ unsigned g_count = 0u;

// Gaussian(sigma=1.5, k=11) normalized fp32 weights
static __device__ constexpr float WT[KS] = {
    0.00102838f, 0.00759876f, 0.03600077f, 0.10936069f, 0.21300554f,
    0.26601172f,
    0.21300554f, 0.10936069f, 0.03600077f, 0.00759876f, 0.00102838f
};

__device__ __forceinline__ u64 pack2(float lo, float hi) {
    u64 r; asm("mov.b64 %0,{%1,%2};" : "=l"(r) : "f"(lo), "f"(hi)); return r;
}
__device__ __forceinline__ void unpack2(u64 v, float& lo, float& hi) {
    asm("mov.b64 {%0,%1},%2;" : "=f"(lo), "=f"(hi) : "l"(v));
}
__device__ __forceinline__ u64 fma2(u64 a, u64 b, u64 c) {
    u64 r; asm("fma.rn.f32x2 %0,%1,%2,%3;" : "=l"(r) : "l"(a), "l"(b), "l"(c)); return r;
}

extern __shared__ unsigned char smem_raw[];

__launch_bounds__(128)
__global__ void ssim_kernel(const float* __restrict__ X, const float* __restrict__ Y,
                            float* __restrict__ out) {
    u64* buf01 = (u64*)smem_raw;                  // (mu_x, mu_y) after vertical blur
    u64* buf23 = buf01 + OUT_ROWS * PITCH + 8;    // (x2+y2, xy)  after vertical blur
    float* warpsums = (float*)(buf23 + OUT_ROWS * PITCH + 8);

    const int tid   = threadIdx.x;
    const int plane = blockIdx.z;
    const int c0    = blockIdx.x * OUT_COLS;
    const int r0    = blockIdx.y * OUT_ROWS;

    const float* __restrict__ xp = X + (size_t)plane * IMG_W * IMG_W;
    const float* __restrict__ yp = Y + (size_t)plane * IMG_W * IMG_W;

    u64 wp[KS];
    #pragma unroll
    for (int k = 0; k < KS; k++) wp[k] = pack2(WT[k], WT[k]);

    // ============ Pass 1: vertical sliding blur, thread = one column ============
    {
        const int  c     = tid;                       // 0..127
        const int  gc    = c0 + c;
        const bool colok = gc < IMG_W;
        const float* __restrict__ xcol = xp + gc;
        const float* __restrict__ ycol = yp + gc;

        u64 a01[KS], a23[KS];
        #pragma unroll
        for (int j = 0; j < KS; j++) { a01[j] = 0ull; a23[j] = 0ull; }

        #pragma unroll
        for (int i = 0; i < IN_ROWS; i++) {
            const int  gr = r0 + i;
            const bool ok = colok && (gr < IMG_W);
            float vx = ok ? __ldg(xcol + gr * IMG_W) : 0.f;
            float vy = ok ? __ldg(ycol + gr * IMG_W) : 0.f;
            u64 v01 = pack2(vx, vy);
            float ss = fmaf(vx, vx, vy * vy);         // x^2 + y^2
            float pp = vx * vy;                       // x*y
            u64 v23 = pack2(ss, pp);

            const int jlo = (10 - i) > 0 ? (10 - i) : 0;
            const int jhi = (IN_ROWS - 1 - i) < 10 ? (IN_ROWS - 1 - i) : 10;
            #pragma unroll
            for (int j = 0; j < KS; j++) {
                if (j >= jlo && j <= jhi) {
                    a01[j] = fma2(wp[10 - j], v01, a01[j]);
                    a23[j] = fma2(wp[10 - j], v23, a23[j]);
                }
            }
            if (i >= 10) {                            // emit output row i-10
                buf01[(i - 10) * PITCH + c] = a01[0];
                buf23[(i - 10) * PITCH + c] = a23[0];
            }
            #pragma unroll
            for (int j = 0; j < KS - 1; j++) { a01[j] = a01[j + 1]; a23[j] = a23[j + 1]; }
            a01[KS - 1] = 0ull; a23[KS - 1] = 0ull;
        }
    }

    __syncthreads();

    // ============ Pass 2: horizontal sliding blur + SSIM, thread = (row, segment) ============
    float acc = 0.f;
    {
        const int r    = tid & 7;                     // smem row (0..7)
        const int seg  = tid >> 3;                    // 0..15
        const int segc = seg * SEGL;                  // first local column of segment
        const bool rowok = (r0 + r) < OUTW;
        const u64* row01 = buf01 + r * PITCH;
        const u64* row23 = buf23 + r * PITCH;

        u64 b01[KS], b23[KS];
        #pragma unroll
        for (int j = 0; j < KS; j++) { b01[j] = 0ull; b23[j] = 0ull; }

        #pragma unroll
        for (int s = 0; s < SEGL + 10; s++) {
            int col = segc + s;
            if (col > IN_COLS - 1) col = IN_COLS - 1; // clamp (feeds only dead outputs)
            u64 l01 = row01[col];
            u64 l23 = row23[col];

            const int jlo = (10 - s) > 0 ? (10 - s) : 0;
            const int jhi = (SEGL + 9 - s) < 10 ? (SEGL + 9 - s) : 10;
            #pragma unroll
            for (int j = 0; j < KS; j++) {
                if (j >= jlo && j <= jhi) {
                    b01[j] = fma2(wp[10 - j], l01, b01[j]);
                    b23[j] = fma2(wp[10 - j], l23, b23[j]);
                }
            }
            if (s >= 10) {
                const int lout = segc + (s - 10);     // local output column
                if (rowok && lout < OUT_COLS && (c0 + lout) < OUTW) {
                    float mux, muy, sxy, exy;
                    unpack2(b01[0], mux, muy);
                    unpack2(b23[0], sxy, exy);
                    float mux2 = mux * mux;
                    float muy2 = muy * muy;
                    float muxy = mux * muy;
                    float cov  = exy - muxy;
                    float t    = mux2 + muy2;
                    float A    = fmaf(2.f, muxy, 1e-4f);
                    float B    = fmaf(2.f, cov,  9e-4f);
                    float D1   = t + 1e-4f;
                    float D2   = (sxy - t) + 9e-4f;
                    acc += __fdividef(A * B, D1 * D2);
                }
            }
            #pragma unroll
            for (int j = 0; j < KS - 1; j++) { b01[j] = b01[j + 1]; b23[j] = b23[j + 1]; }
            b01[KS - 1] = 0ull; b23[KS - 1] = 0ull;
        }
    }

    // ============ Block reduce -> global atomic -> last-block finalize ============
    #pragma unroll
    for (int off = 16; off > 0; off >>= 1)
        acc += __shfl_down_sync(0xffffffffu, acc, off);
    if ((tid & 31) == 0) warpsums[tid >> 5] = acc;
    __syncthreads();
    if (tid == 0) {
        const double inv_n_scale = (double)NPLANE * (double)OUTW * (double)OUTW;
        float blocksum = (warpsums[0] + warpsums[1]) + (warpsums[2] + warpsums[3]);
        atomicAdd(&g_acc, (double)blocksum);
        __threadfence();
        unsigned prev = atomicAdd(&g_count, 1u);
        if (prev == NBLOCKS - 1) {                    // last block finalizes + resets
            double total = atomicAdd(&g_acc, 0.0);    // coherent read
            out[0] = (float)(1.0 - total / inv_n_scale);
            g_acc   = 0.0;                            // restore invariant for next replay
            g_count = 0u;
        }
    }
}

extern "C" void kernel_launch(void* const* d_in, const int* in_sizes, int n_in,
                              void* d_out, int out_size) {
    const float* x = (const float*)d_in[0];
    const float* y = (const float*)d_in[1];
    float* out = (float*)d_out;

    const int smem_bytes = 2 * (OUT_ROWS * PITCH + 8) * 8 + 64;   // ~16.7 KB
    cudaFuncSetAttribute(ssim_kernel, cudaFuncAttributeMaxDynamicSharedMemorySize, smem_bytes);

    dim3 grid(GX, GY, NPLANE);   // 5 x 63 x 48 = 15120 blocks
    ssim_kernel<<<grid, 128, smem_bytes>>>(x, y, out);
}

// round 10
// speedup vs baseline: 1.0660x; 1.0660x over previous
#include <cuda_runtime.h>
#include <cstdint>

#define IMG_W    512
#define OUTW     502
#define NPLANE   48
#define IN_COLS  128
#define OUT_COLS 118
#define OUT_ROWS 16
#define IN_ROWS  26          // OUT_ROWS + 10
#define PITCH    129         // cells (16 B) per smem row; odd -> conflict-free phases
#define KS       11
#define SEGL     15          // outputs per thread in pass 2 (8 segs x 15 = 120 >= 118)
#define GX       5
#define GY       32
#define NBLOCKS  (GX * GY * NPLANE)   // 7680

typedef unsigned long long u64;
typedef unsigned int       u32;

__device__ double   g_acc   = 0.0;
__device__ unsigned g_count = 0u;

// Gaussian(sigma=1.5, k=11) normalized fp32 weights
static __device__ constexpr float WT[KS] = {
    0.00102838f, 0.00759876f, 0.03600077f, 0.10936069f, 0.21300554f,
    0.26601172f,
    0.21300554f, 0.10936069f, 0.03600077f, 0.00759876f, 0.00102838f
};

__device__ __forceinline__ u64 pack2(float lo, float hi) {
    u64 r; asm("mov.b64 %0,{%1,%2};" : "=l"(r) : "f"(lo), "f"(hi)); return r;
}
__device__ __forceinline__ void unpack2(u64 v, float& lo, float& hi) {
    asm("mov.b64 {%0,%1},%2;" : "=f"(lo), "=f"(hi) : "l"(v));
}
__device__ __forceinline__ u64 fma2(u64 a, u64 b, u64 c) {
    u64 r; asm("fma.rn.f32x2 %0,%1,%2,%3;" : "=l"(r) : "l"(a), "l"(b), "l"(c)); return r;
}
// 16B smem cell store: {v01, v23}
__device__ __forceinline__ void sts128(u32 addr, u64 a, u64 b) {
    u32 a0, a1, b0, b1;
    asm("mov.b64 {%0,%1},%2;" : "=r"(a0), "=r"(a1) : "l"(a));
    asm("mov.b64 {%0,%1},%2;" : "=r"(b0), "=r"(b1) : "l"(b));
    asm volatile("st.shared.v4.b32 [%0],{%1,%2,%3,%4};"
                 :: "r"(addr), "r"(a0), "r"(a1), "r"(b0), "r"(b1));
}
__device__ __forceinline__ void lds128(u32 addr, u64& a, u64& b) {
    u32 a0, a1, b0, b1;
    asm volatile("ld.shared.v4.b32 {%0,%1,%2,%3},[%4];"
                 : "=r"(a0), "=r"(a1), "=r"(b0), "=r"(b1) : "r"(addr));
    asm("mov.b64 %0,{%1,%2};" : "=l"(a) : "r"(a0), "r"(a1));
    asm("mov.b64 %0,{%1,%2};" : "=l"(b) : "r"(b0), "r"(b1));
}

extern __shared__ unsigned char smem_raw[];   // OUT_ROWS * PITCH * 16 bytes of cells

// Pass 1: vertical sliding blur of {(x,y),(x2+y2,xy)}; thread owns one column.
// GUARD=false for fully-interior blocks (no bounds predication in the hot loop).
template <bool GUARD>
__device__ __forceinline__ void pass1_body(const float* __restrict__ xcol,
                                           const float* __restrict__ ycol,
                                           int r0, bool colok, u32 cell_addr,
                                           const u64* wp) {
    u64 a01[KS], a23[KS];
    #pragma unroll
    for (int j = 0; j < KS; j++) { a01[j] = 0ull; a23[j] = 0ull; }

    #pragma unroll
    for (int i = 0; i < IN_ROWS; i++) {
        const int gr = r0 + i;
        float vx, vy;
        if (GUARD) {
            const bool ok = colok && (gr < IMG_W);
            vx = ok ? __ldg(xcol + gr * IMG_W) : 0.f;
            vy = ok ? __ldg(ycol + gr * IMG_W) : 0.f;
        } else {
            vx = __ldg(xcol + gr * IMG_W);
            vy = __ldg(ycol + gr * IMG_W);
        }
        u64 v01 = pack2(vx, vy);
        u64 v23 = pack2(fmaf(vx, vx, vy * vy), vx * vy);

        const int jlo = (10 - i) > 0 ? (10 - i) : 0;
        const int jhi = (IN_ROWS - 1 - i) < 10 ? (IN_ROWS - 1 - i) : 10;
        #pragma unroll
        for (int j = 0; j < KS; j++) {
            if (j >= jlo && j <= jhi) {
                a01[j] = fma2(wp[10 - j], v01, a01[j]);
                a23[j] = fma2(wp[10 - j], v23, a23[j]);
            }
        }
        if (i >= 10) {                         // emit output row i-10
            sts128(cell_addr + (i - 10) * (PITCH * 16), a01[0], a23[0]);
        }
        #pragma unroll
        for (int j = 0; j < KS - 1; j++) { a01[j] = a01[j + 1]; a23[j] = a23[j + 1]; }
        a01[KS - 1] = 0ull; a23[KS - 1] = 0ull;
    }
}

__launch_bounds__(128)
__global__ void ssim_kernel(const float* __restrict__ X, const float* __restrict__ Y,
                            float* __restrict__ out) {
    __shared__ float warpsums[4];
    const u32 sbase = (u32)__cvta_generic_to_shared(smem_raw);

    const int tid   = threadIdx.x;
    const int plane = blockIdx.z;
    const int c0    = blockIdx.x * OUT_COLS;
    const int r0    = blockIdx.y * OUT_ROWS;

    const float* __restrict__ xp = X + (size_t)plane * IMG_W * IMG_W;
    const float* __restrict__ yp = Y + (size_t)plane * IMG_W * IMG_W;

    u64 wp[KS];
    #pragma unroll
    for (int k = 0; k < KS; k++) wp[k] = pack2(WT[k], WT[k]);

    // ============ Pass 1 ============
    {
        const int  c     = tid;                       // 0..127
        const int  gc    = c0 + c;
        const bool colok = gc < IMG_W;
        const u32  cell_addr = sbase + c * 16;
        const bool interior = (c0 + IN_COLS <= IMG_W) && (r0 + IN_ROWS <= IMG_W);
        if (interior) pass1_body<false>(xp + gc, yp + gc, r0, true,  cell_addr, wp);
        else          pass1_body<true >(xp + gc, yp + gc, r0, colok, cell_addr, wp);
    }

    __syncthreads();

    // ============ Pass 2: horizontal sliding blur + SSIM ============
    float acc = 0.f;
    {
        const int  r     = tid & 15;                  // smem row (0..15)
        const int  seg   = tid >> 4;                  // 0..7
        const int  segc  = seg * SEGL;                // 0,15,...,105
        const bool rowok = (r0 + r) < OUTW;
        const u32  rowaddr = sbase + r * (PITCH * 16);

        u64 b01[KS], b23[KS];
        #pragma unroll
        for (int j = 0; j < KS; j++) { b01[j] = 0ull; b23[j] = 0ull; }

        #pragma unroll
        for (int s = 0; s < SEGL + 10; s++) {
            int col = segc + s;
            if (col > IN_COLS - 1) col = IN_COLS - 1; // clamp (feeds only dead outputs)
            u64 l01, l23;
            lds128(rowaddr + col * 16, l01, l23);

            const int jlo = (10 - s) > 0 ? (10 - s) : 0;
            const int jhi = (SEGL + 9 - s) < 10 ? (SEGL + 9 - s) : 10;
            #pragma unroll
            for (int j = 0; j < KS; j++) {
                if (j >= jlo && j <= jhi) {
                    b01[j] = fma2(wp[10 - j], l01, b01[j]);
                    b23[j] = fma2(wp[10 - j], l23, b23[j]);
                }
            }
            if (s >= 10) {
                const int lout = segc + (s - 10);     // local output column
                if (rowok && lout < OUT_COLS && (c0 + lout) < OUTW) {
                    float mux, muy, sxy, exy;
                    unpack2(b01[0], mux, muy);
                    unpack2(b23[0], sxy, exy);
                    float mux2 = mux * mux;
                    float muy2 = muy * muy;
                    float muxy = mux * muy;
                    float cov  = exy - muxy;
                    float t    = mux2 + muy2;
                    float A    = fmaf(2.f, muxy, 1e-4f);
                    float B    = fmaf(2.f, cov,  9e-4f);
                    float D1   = t + 1e-4f;
                    float D2   = (sxy - t) + 9e-4f;
                    acc += __fdividef(A * B, D1 * D2);
                }
            }
            #pragma unroll
            for (int j = 0; j < KS - 1; j++) { b01[j] = b01[j + 1]; b23[j] = b23[j + 1]; }
            b01[KS - 1] = 0ull; b23[KS - 1] = 0ull;
        }
    }

    // ============ Block reduce -> global atomic -> last-block finalize ============
    #pragma unroll
    for (int off = 16; off > 0; off >>= 1)
        acc += __shfl_down_sync(0xffffffffu, acc, off);
    if ((tid & 31) == 0) warpsums[tid >> 5] = acc;
    __syncthreads();
    if (tid == 0) {
        float blocksum = (warpsums[0] + warpsums[1]) + (warpsums[2] + warpsums[3]);
        atomicAdd(&g_acc, (double)blocksum);
        __threadfence();
        unsigned prev = atomicAdd(&g_count, 1u);
        if (prev == NBLOCKS - 1) {                    // last block finalizes + resets
            double total = atomicAdd(&g_acc, 0.0);    // coherent read
            const double n = (double)NPLANE * (double)OUTW * (double)OUTW;
            out[0] = (float)(1.0 - total / n);
            g_acc   = 0.0;                            // restore invariant for next replay
            g_count = 0u;
        }
    }
}

extern "C" void kernel_launch(void* const* d_in, const int* in_sizes, int n_in,
                              void* d_out, int out_size) {
    const float* x = (const float*)d_in[0];
    const float* y = (const float*)d_in[1];
    float* out = (float*)d_out;

    const int smem_bytes = OUT_ROWS * PITCH * 16;     // 33,024 B of 16B cells
    cudaFuncSetAttribute(ssim_kernel, cudaFuncAttributeMaxDynamicSharedMemorySize, smem_bytes);

    dim3 grid(GX, GY, NPLANE);   // 5 x 32 x 48 = 7680 blocks
    ssim_kernel<<<grid, 128, smem_bytes>>>(x, y, out);
}